// round 16
// baseline (speedup 1.0000x reference)
#include <cuda_runtime.h>
#include <cuda_bf16.h>
#include <cstdint>

// ---------------------------------------------------------------------------
// APPNP dense surrogate, N=8192, F=MLP=512, C=256, 10 power iters, alpha=0.1.
// sm_103 (non-'a'): legacy mma only. bf16 HMMA saturates at ~128 MAC/cyc/SMSP
// (5 mainloop variants all pinned there). v8 = proven v4 bf16 GEMM for the
// MLP/A-GEMMs + int8 IMMA (m16n8k32.s8, historically 2x bf16 rate) for the
// 10 power iterations (65% of FLOPs).
// int8 validity: A in [0, 2/N] with exact sup -> fixed scale SA8;
// A row-sums ~1 => |z| non-increasing => one z-scale from z0 serves all iters.
// Precision bound: R10's fp8 (worse per-entry ulp) measured rel_err 1.59e-4.
// Transposed-activation layout: B operand always K-major [N,K].
// ---------------------------------------------------------------------------

#define NN   8192
#define FD   512
#define CD   256
#define ALPHA 0.1f
#define SA8  520192.0f       // 127 / (2/8192)

#define BKr  64
#define STRB 144             // smem row stride bytes (both bf16-64 and s8-128 tiles)

// ---- scratch ---------------------------------------------------------------
__device__ __nv_bfloat16 g_Abf[(size_t)NN * NN];     // 128 MB
__device__ int8_t        g_A8 [(size_t)NN * NN];     // 64 MB
__device__ __nv_bfloat16 g_Fbf[(size_t)NN * FD];
__device__ __nv_bfloat16 g_W0t[FD * FD];
__device__ __nv_bfloat16 g_W1t[FD * FD];
__device__ __nv_bfloat16 g_Wot[FD * CD];
__device__ __nv_bfloat16 g_Yt[(size_t)FD * NN];
__device__ __nv_bfloat16 g_X[(size_t)NN * FD];
__device__ __nv_bfloat16 g_Z0t[(size_t)CD * NN];
__device__ __nv_bfloat16 g_Za[(size_t)CD * NN];      // bf16 power output (last iter read)
__device__ int8_t        g_Qa[(size_t)CD * NN];      // int8 z ring
__device__ int8_t        g_Qb[(size_t)CD * NN];
__device__ float         g_zmax;

__device__ __forceinline__ uint32_t sptr(const void* p) {
    return (uint32_t)__cvta_generic_to_shared(p);
}
__device__ __forceinline__ void ldsm4(uint32_t a, uint32_t* r) {
    asm volatile("ldmatrix.sync.aligned.m8n8.x4.shared.b16 {%0,%1,%2,%3}, [%4];"
                 : "=r"(r[0]), "=r"(r[1]), "=r"(r[2]), "=r"(r[3]) : "r"(a));
}

// ---- converts --------------------------------------------------------------
__global__ void f32_to_bf16_kernel(const float* __restrict__ src,
                                   __nv_bfloat16* __restrict__ dst, long n8) {
    long t = (long)blockIdx.x * blockDim.x + threadIdx.x;
    if (t >= n8) return;
    long i = t * 8;
    float4 a = *(const float4*)(src + i);
    float4 b = *(const float4*)(src + i + 4);
    union { int4 v; __nv_bfloat16 h[8]; } u;
    u.h[0] = __float2bfloat16(a.x); u.h[1] = __float2bfloat16(a.y);
    u.h[2] = __float2bfloat16(a.z); u.h[3] = __float2bfloat16(a.w);
    u.h[4] = __float2bfloat16(b.x); u.h[5] = __float2bfloat16(b.y);
    u.h[6] = __float2bfloat16(b.z); u.h[7] = __float2bfloat16(b.w);
    *(int4*)(dst + i) = u.v;
}

// fltr -> bf16 AND int8 in one pass (single 256MB read)
__global__ void cvtA_dual_kernel(const float* __restrict__ src,
                                 __nv_bfloat16* __restrict__ db,
                                 int8_t* __restrict__ dq, long n8) {
    long t = (long)blockIdx.x * blockDim.x + threadIdx.x;
    if (t >= n8) return;
    long i = t * 8;
    float f[8];
    *(float4*)(f)     = *(const float4*)(src + i);
    *(float4*)(f + 4) = *(const float4*)(src + i + 4);
    union { int4 v; __nv_bfloat16 h[8]; } u;
    union { uint2 v; int8_t q[8]; } w;
#pragma unroll
    for (int j = 0; j < 8; j++) {
        u.h[j] = __float2bfloat16(f[j]);
        int q = __float2int_rn(f[j] * SA8);
        w.q[j] = (int8_t)(q > 127 ? 127 : q);
    }
    *(int4*)(db + i) = u.v;
    *(uint2*)(dq + i) = w.v;
}

__global__ void wcvt_T_kernel(const float* __restrict__ W0,
                              const float* __restrict__ W1,
                              const float* __restrict__ Wo,
                              __nv_bfloat16* __restrict__ W0t,
                              __nv_bfloat16* __restrict__ W1t,
                              __nv_bfloat16* __restrict__ Wot) {
    __shared__ float t[32][33];
    const float* src; __nv_bfloat16* dst; int C;
    if (blockIdx.z == 0)      { src = W0; dst = W0t; C = FD; }
    else if (blockIdx.z == 1) { src = W1; dst = W1t; C = FD; }
    else                      { src = Wo; dst = Wot; C = CD; }
    int c0 = blockIdx.x * 32, r0 = blockIdx.y * 32;
    if (c0 >= C) return;
    int tx = threadIdx.x, ty = threadIdx.y;   // (32, 8)
#pragma unroll
    for (int j = 0; j < 32; j += 8)
        t[ty + j][tx] = src[(size_t)(r0 + ty + j) * C + c0 + tx];
    __syncthreads();
#pragma unroll
    for (int j = 0; j < 32; j += 8)
        dst[(size_t)(c0 + ty + j) * FD + r0 + tx] = __float2bfloat16(t[tx][ty + j]);
}

__global__ void init_kernel() { g_zmax = 0.f; }     // reset per replay (launch #4)

// max|z0| -> g_zmax (atomicMax on positive-float bits)
__global__ void zmax_kernel(const __nv_bfloat16* __restrict__ Z) {
    long t = (long)blockIdx.x * blockDim.x + threadIdx.x;
    float m = 0.f;
    const long total = (long)CD * NN / 8;
#pragma unroll 4
    for (long i = t; i < total; i += (long)gridDim.x * blockDim.x) {
        union { int4 v; __nv_bfloat162 h[4]; } u;
        u.v = *(const int4*)(Z + i * 8);
#pragma unroll
        for (int j = 0; j < 4; j++) {
            m = fmaxf(m, fabsf(__bfloat162float(u.h[j].x)));
            m = fmaxf(m, fabsf(__bfloat162float(u.h[j].y)));
        }
    }
#pragma unroll
    for (int o = 16; o > 0; o >>= 1) m = fmaxf(m, __shfl_xor_sync(0xffffffffu, m, o));
    if ((threadIdx.x & 31) == 0) atomicMax((int*)&g_zmax, __float_as_int(m));
}

// z0 bf16 -> int8 (scale 127/zmax)
__global__ void quantZ_kernel(const __nv_bfloat16* __restrict__ Z,
                              int8_t* __restrict__ Q) {
    long t = (long)blockIdx.x * blockDim.x + threadIdx.x;
    if (t >= (long)CD * NN / 8) return;
    float s = 127.f / g_zmax;
    long i = t * 8;
    union { int4 v; __nv_bfloat162 h[4]; } u;
    u.v = *(const int4*)(Z + i);
    union { uint2 v; int8_t q[8]; } w;
#pragma unroll
    for (int j = 0; j < 4; j++) {
        int q0 = __float2int_rn(__bfloat162float(u.h[j].x) * s);
        int q1 = __float2int_rn(__bfloat162float(u.h[j].y) * s);
        w.q[2 * j]     = (int8_t)max(-127, min(127, q0));
        w.q[2 * j + 1] = (int8_t)max(-127, min(127, q1));
    }
    *(uint2*)(Q + i) = w.v;
}

// ---- v4 bf16 GEMM (proven, 2021us config): C = epi(Aop @ B), Bt[N,K] ------
// MODE 0: acc + bias[row]   MODE 1: relu(acc)
#define A_TILE_B (64 * STRB)
#define STG_B    ((64 + 128) * STRB)
#define NSTG 4
#define SMEM_TOT (NSTG * STG_B)          // 110592 -> 2 CTAs/SM

template <int MODE>
__global__ void __launch_bounds__(256, 2)
gemm_v4(const __nv_bfloat16* __restrict__ Aop,
        const __nv_bfloat16* __restrict__ Btp,
        __nv_bfloat16* __restrict__ Cmat,
        int M, int N, int K,
        const float* __restrict__ bias) {
    extern __shared__ char sm[];
    const uint32_t base = sptr(sm);

    const int tid  = threadIdx.x;
    const int lane = tid & 31;
    const int warp = tid >> 5;
    const int wm = (warp & 1) * 32;
    const int wn = (warp >> 1) * 32;
    const int bm0 = blockIdx.y * 64;
    const int bn0 = blockIdx.x * 128;
    const int nIter = K / BKr;

    auto load_stage = [&](int st, int kiter) {
        const int k0 = kiter * BKr;
        const uint32_t sa = base + st * STG_B;
        const uint32_t sb = sa + A_TILE_B;
#pragma unroll
        for (int i = 0; i < 2; i++) {
            int id = tid + i * 256, row = id >> 3, c = id & 7;
            const void* g = Aop + (size_t)(bm0 + row) * K + k0 + c * 8;
            asm volatile("cp.async.cg.shared.global [%0], [%1], 16;\n"
                         :: "r"(sa + row * STRB + c * 16), "l"(g));
        }
#pragma unroll
        for (int i = 0; i < 4; i++) {
            int id = tid + i * 256, row = id >> 3, c = id & 7;
            const void* g = Btp + (size_t)(bn0 + row) * K + k0 + c * 8;
            asm volatile("cp.async.cg.shared.global [%0], [%1], 16;\n"
                         :: "r"(sb + row * STRB + c * 16), "l"(g));
        }
        asm volatile("cp.async.commit_group;\n");
    };

    const int lrow   = (lane & 7) + ((lane >> 3) & 1) * 8;
    const int lcol16 = (lane >> 4) * 16;
    const uint32_t aoff = (uint32_t)(wm + lrow) * STRB + lcol16;
    const uint32_t boff = (uint32_t)(wn + lrow) * STRB + lcol16;

    float acc[2][4][4];
#pragma unroll
    for (int i = 0; i < 2; i++)
#pragma unroll
        for (int j = 0; j < 4; j++)
#pragma unroll
            for (int k = 0; k < 4; k++) acc[i][j][k] = 0.f;

    load_stage(0, 0);
    load_stage(1, 1);
    load_stage(2, 2);

    for (int it = 0; it < nIter; it++) {
        asm volatile("cp.async.wait_group %0;\n" :: "n"(NSTG - 2));
        __syncthreads();

        int nxt = it + NSTG - 1;
        if (nxt < nIter) load_stage(nxt & (NSTG - 1), nxt);
        else asm volatile("cp.async.commit_group;\n");

        const uint32_t sa = base + (it & (NSTG - 1)) * STG_B;
        const uint32_t sb = sa + A_TILE_B;

#pragma unroll
        for (int kk = 0; kk < BKr / 16; kk++) {
            uint32_t af[2][4], bf[2][4];
#pragma unroll
            for (int mi = 0; mi < 2; mi++)
                ldsm4(sa + aoff + mi * 16 * STRB + kk * 32, af[mi]);
#pragma unroll
            for (int nb = 0; nb < 2; nb++)
                ldsm4(sb + boff + nb * 16 * STRB + kk * 32, bf[nb]);
#pragma unroll
            for (int mi = 0; mi < 2; mi++)
#pragma unroll
                for (int nj = 0; nj < 4; nj++) {
                    uint32_t b0 = bf[nj >> 1][nj & 1];
                    uint32_t b1 = bf[nj >> 1][2 + (nj & 1)];
                    asm volatile(
                        "mma.sync.aligned.m16n8k16.row.col.f32.bf16.bf16.f32 "
                        "{%0,%1,%2,%3}, {%4,%5,%6,%7}, {%8,%9}, {%0,%1,%2,%3};\n"
                        : "+f"(acc[mi][nj][0]), "+f"(acc[mi][nj][1]),
                          "+f"(acc[mi][nj][2]), "+f"(acc[mi][nj][3])
                        : "r"(af[mi][0]), "r"(af[mi][1]),
                          "r"(af[mi][2]), "r"(af[mi][3]),
                          "r"(b0), "r"(b1));
                }
        }
    }

#pragma unroll
    for (int mi = 0; mi < 2; mi++) {
#pragma unroll
        for (int nj = 0; nj < 4; nj++) {
            int row0 = bm0 + wm + mi * 16 + (lane >> 2);
            int col  = bn0 + wn + nj * 8 + (lane & 3) * 2;
#pragma unroll
            for (int h = 0; h < 2; h++) {
                int row = row0 + h * 8;
                float v0 = acc[mi][nj][2 * h + 0];
                float v1 = acc[mi][nj][2 * h + 1];
                if (MODE == 0) { float b = bias[row]; v0 += b; v1 += b; }
                if (MODE == 1) { v0 = fmaxf(v0, 0.f); v1 = fmaxf(v1, 0.f); }
                *(__nv_bfloat162*)(Cmat + (size_t)row * N + col) = __floats2bfloat162_rn(v0, v1);
            }
        }
    }
}

// ---- int8 IMMA power-iteration GEMM ---------------------------------------
// Zt_new = 0.9/(SA8*SZ8) * (Qin @ A8t) + 0.1*Z0;  writes bf16 + int8(next).
// Same geometry as v4: CTA 64x128, KB=128 int8 (=128B rows), nIter=64, NST=4.
__global__ void __launch_bounds__(256, 2)
gemm_i8pow(const int8_t* __restrict__ Qin,
           const int8_t* __restrict__ A8,
           __nv_bfloat16* __restrict__ Zout,
           int8_t* __restrict__ Qout,
           const __nv_bfloat16* __restrict__ Z0) {
    constexpr int KB = 128;              // int8 elems per block = 128 bytes
    const int N = NN, K = NN;

    extern __shared__ char sm[];
    const uint32_t base = sptr(sm);

    const int tid  = threadIdx.x;
    const int lane = tid & 31;
    const int warp = tid >> 5;
    const int wm = (warp & 1) * 32;
    const int wn = (warp >> 1) * 32;
    const int bm0 = blockIdx.y * 64;
    const int bn0 = blockIdx.x * 128;
    const int nIter = K / KB;            // 64

    auto load_stage = [&](int st, int kiter) {
        const int k0 = kiter * KB;
        const uint32_t sa = base + st * STG_B;
        const uint32_t sb = sa + A_TILE_B;
#pragma unroll
        for (int i = 0; i < 2; i++) {     // A: 64 rows x 8 16B chunks
            int id = tid + i * 256, row = id >> 3, c = id & 7;
            const void* g = Qin + (size_t)(bm0 + row) * K + k0 + c * 16;
            asm volatile("cp.async.cg.shared.global [%0], [%1], 16;\n"
                         :: "r"(sa + row * STRB + c * 16), "l"(g));
        }
#pragma unroll
        for (int i = 0; i < 4; i++) {     // B: 128 rows x 8 chunks
            int id = tid + i * 256, row = id >> 3, c = id & 7;
            const void* g = A8 + (size_t)(bn0 + row) * K + k0 + c * 16;
            asm volatile("cp.async.cg.shared.global [%0], [%1], 16;\n"
                         :: "r"(sb + row * STRB + c * 16), "l"(g));
        }
        asm volatile("cp.async.commit_group;\n");
    };

    const int lrow   = (lane & 7) + ((lane >> 3) & 1) * 8;
    const int lcol16 = (lane >> 4) * 16;
    const uint32_t aoff = (uint32_t)(wm + lrow) * STRB + lcol16;
    const uint32_t boff = (uint32_t)(wn + lrow) * STRB + lcol16;

    int acc[2][4][4];
#pragma unroll
    for (int i = 0; i < 2; i++)
#pragma unroll
        for (int j = 0; j < 4; j++)
#pragma unroll
            for (int k = 0; k < 4; k++) acc[i][j][k] = 0;

    load_stage(0, 0);
    load_stage(1, 1);
    load_stage(2, 2);

    for (int it = 0; it < nIter; it++) {
        asm volatile("cp.async.wait_group %0;\n" :: "n"(NSTG - 2));
        __syncthreads();

        int nxt = it + NSTG - 1;
        if (nxt < nIter) load_stage(nxt & (NSTG - 1), nxt);
        else asm volatile("cp.async.commit_group;\n");

        const uint32_t sa = base + (it & (NSTG - 1)) * STG_B;
        const uint32_t sb = sa + A_TILE_B;

#pragma unroll
        for (int kk = 0; kk < KB / 32; kk++) {   // 4 k32 steps, 32B each
            uint32_t af[2][4], bf[2][4];
#pragma unroll
            for (int mi = 0; mi < 2; mi++)
                ldsm4(sa + aoff + mi * 16 * STRB + kk * 32, af[mi]);
#pragma unroll
            for (int nb = 0; nb < 2; nb++)
                ldsm4(sb + boff + nb * 16 * STRB + kk * 32, bf[nb]);
            // s8 frag mapping identical to bf16 (4 s8 <-> 2 bf16 per reg)
#pragma unroll
            for (int mi = 0; mi < 2; mi++)
#pragma unroll
                for (int nj = 0; nj < 4; nj++) {
                    uint32_t b0 = bf[nj >> 1][nj & 1];
                    uint32_t b1 = bf[nj >> 1][2 + (nj & 1)];
                    asm volatile(
                        "mma.sync.aligned.m16n8k32.row.col.s32.s8.s8.s32 "
                        "{%0,%1,%2,%3}, {%4,%5,%6,%7}, {%8,%9}, {%0,%1,%2,%3};\n"
                        : "+r"(acc[mi][nj][0]), "+r"(acc[mi][nj][1]),
                          "+r"(acc[mi][nj][2]), "+r"(acc[mi][nj][3])
                        : "r"(af[mi][0]), "r"(af[mi][1]),
                          "r"(af[mi][2]), "r"(af[mi][3]),
                          "r"(b0), "r"(b1));
                }
        }
    }

    // epilogue: dequant + APPNP mix + bf16 store + requant int8 store
    const float zmax = g_zmax;
    const float SZ8  = 127.f / zmax;
    const float S09  = (1.f - ALPHA) * zmax / (SA8 * 127.f);
#pragma unroll
    for (int mi = 0; mi < 2; mi++) {
#pragma unroll
        for (int nj = 0; nj < 4; nj++) {
            int row0 = bm0 + wm + mi * 16 + (lane >> 2);
            int col  = bn0 + wn + nj * 8 + (lane & 3) * 2;
#pragma unroll
            for (int h = 0; h < 2; h++) {
                int row = row0 + h * 8;
                __nv_bfloat162 z = *(const __nv_bfloat162*)(Z0 + (size_t)row * N + col);
                float v0 = (float)acc[mi][nj][2 * h + 0] * S09 + ALPHA * __bfloat162float(z.x);
                float v1 = (float)acc[mi][nj][2 * h + 1] * S09 + ALPHA * __bfloat162float(z.y);
                *(__nv_bfloat162*)(Zout + (size_t)row * N + col) = __floats2bfloat162_rn(v0, v1);
                int q0 = max(-127, min(127, __float2int_rn(v0 * SZ8)));
                int q1 = max(-127, min(127, __float2int_rn(v1 * SZ8)));
                uint16_t pk = (uint16_t)((q0 & 0xFF) | ((q1 & 0xFF) << 8));
                *(uint16_t*)(Qout + (size_t)row * N + col) = pk;
            }
        }
    }
}

// ---- column softmax of Zt[256, 8192] -> out[8192, 256] fp32 ---------------
__global__ void softmax_T_kernel(const __nv_bfloat16* __restrict__ Zt,
                                 float* __restrict__ out) {
    __shared__ float tile[2][32][33];
    int warp = threadIdx.x >> 5, lane = threadIdx.x & 31;
    int n0 = blockIdx.x * 64 + warp * 32;
    int n = n0 + lane;

    float mx = -1e30f;
#pragma unroll 8
    for (int c = 0; c < CD; c++)
        mx = fmaxf(mx, __bfloat162float(Zt[(size_t)c * NN + n]));
    float s = 0.f;
#pragma unroll 8
    for (int c = 0; c < CD; c++)
        s += __expf(__bfloat162float(Zt[(size_t)c * NN + n]) - mx);
    float inv = 1.f / s;

    for (int c0 = 0; c0 < CD; c0 += 32) {
#pragma unroll
        for (int cc = 0; cc < 32; cc++)
            tile[warp][cc][lane] =
                __expf(__bfloat162float(Zt[(size_t)(c0 + cc) * NN + n]) - mx) * inv;
        __syncwarp();
#pragma unroll
        for (int i = 0; i < 32; i++)
            out[(size_t)(n0 + i) * CD + c0 + lane] = tile[warp][lane][i];
        __syncwarp();
    }
}

// ---------------------------------------------------------------------------
extern "C" void kernel_launch(void* const* d_in, const int* in_sizes, int n_in,
                              void* d_out, int out_size) {
    const float* features = (const float*)d_in[0];
    const float* fltr     = (const float*)d_in[1];
    const float* W0       = (const float*)d_in[2];
    const float* b0       = (const float*)d_in[3];
    const float* W1       = (const float*)d_in[4];
    const float* b1       = (const float*)d_in[5];
    const float* Wo       = (const float*)d_in[6];
    const float* bo       = (const float*)d_in[7];

    void *pA, *pA8, *pF, *pW0, *pW1, *pWo, *pYt, *pX, *pZ0, *pZa, *pQa, *pQb;
    cudaGetSymbolAddress(&pA,  g_Abf);
    cudaGetSymbolAddress(&pA8, g_A8);
    cudaGetSymbolAddress(&pF,  g_Fbf);
    cudaGetSymbolAddress(&pW0, g_W0t);
    cudaGetSymbolAddress(&pW1, g_W1t);
    cudaGetSymbolAddress(&pWo, g_Wot);
    cudaGetSymbolAddress(&pYt, g_Yt);
    cudaGetSymbolAddress(&pX,  g_X);
    cudaGetSymbolAddress(&pZ0, g_Z0t);
    cudaGetSymbolAddress(&pZa, g_Za);
    cudaGetSymbolAddress(&pQa, g_Qa);
    cudaGetSymbolAddress(&pQb, g_Qb);

    __nv_bfloat16* Abf = (__nv_bfloat16*)pA;
    int8_t*        A8  = (int8_t*)pA8;
    __nv_bfloat16* Fbf = (__nv_bfloat16*)pF;
    __nv_bfloat16* W0t = (__nv_bfloat16*)pW0;
    __nv_bfloat16* W1t = (__nv_bfloat16*)pW1;
    __nv_bfloat16* Wot = (__nv_bfloat16*)pWo;
    __nv_bfloat16* Yt  = (__nv_bfloat16*)pYt;
    __nv_bfloat16* Xb  = (__nv_bfloat16*)pX;
    __nv_bfloat16* Z0t = (__nv_bfloat16*)pZ0;
    __nv_bfloat16* Za  = (__nv_bfloat16*)pZa;
    int8_t*        Qa  = (int8_t*)pQa;
    int8_t*        Qb  = (int8_t*)pQb;

    cudaFuncSetAttribute(gemm_v4<0>, cudaFuncAttributeMaxDynamicSharedMemorySize, SMEM_TOT);
    cudaFuncSetAttribute(gemm_v4<1>, cudaFuncAttributeMaxDynamicSharedMemorySize, SMEM_TOT);
    cudaFuncSetAttribute(gemm_i8pow, cudaFuncAttributeMaxDynamicSharedMemorySize, SMEM_TOT);

    // 0) converts (launches 1-4)
    {
        long n8 = (long)NN * NN / 8;
        cvtA_dual_kernel<<<(int)((n8 + 255) / 256), 256>>>(fltr, Abf, A8, n8);
        long f8 = (long)NN * FD / 8;
        f32_to_bf16_kernel<<<(int)((f8 + 255) / 256), 256>>>(features, Fbf, f8);
        wcvt_T_kernel<<<dim3(16, 16, 3), dim3(32, 8)>>>(W0, W1, Wo, W0t, W1t, Wot);
        init_kernel<<<1, 1>>>();
    }

    dim3 gridYt(NN / 128, FD / 64);    // (64, 8)  [512,8192]
    dim3 gridX (FD / 128, NN / 64);    // (4, 128) [8192,512]
    dim3 gridZ (NN / 128, CD / 64);    // (64, 4)  [256,8192]

    // 1) Yt = W0t @ Ft (+b0 row)              (launch 5)
    gemm_v4<0><<<gridYt, 256, SMEM_TOT>>>(W0t, Fbf, Yt, FD, NN, FD, b0);
    // 2) X = relu(A @ Y)                      (launch 6 <- ncu capture, K=8192)
    gemm_v4<1><<<gridX, 256, SMEM_TOT>>>(Abf, Yt, Xb, NN, FD, NN, nullptr);
    // 3) Yt = W1t @ Xt (+b1 row)
    gemm_v4<0><<<gridYt, 256, SMEM_TOT>>>(W1t, Xb, Yt, FD, NN, FD, b1);
    // 4) X = relu(A @ Y2)
    gemm_v4<1><<<gridX, 256, SMEM_TOT>>>(Abf, Yt, Xb, NN, FD, NN, nullptr);
    // 5) Z0t = Wot @ X2t (+bo row)
    gemm_v4<0><<<gridZ, 256, SMEM_TOT>>>(Wot, Xb, Z0t, CD, NN, FD, bo);

    // 5b) z scale + quantize z0
    zmax_kernel<<<256, 256>>>(Z0t);
    {
        long z8 = (long)CD * NN / 8;
        quantZ_kernel<<<(int)((z8 + 255) / 256), 256>>>(Z0t, Qa);
    }

    // 6) 10x int8: Zt = 0.9 * Zt @ At + 0.1 * Z0t
    int8_t* qin = Qa;
    int8_t* qout = Qb;
    for (int it = 0; it < 10; it++) {
        gemm_i8pow<<<gridZ, 256, SMEM_TOT>>>(qin, A8, Za, qout, Z0t);
        int8_t* t = qin; qin = qout; qout = t;
    }

    // 7) column softmax -> [8192, 256] fp32
    softmax_T_kernel<<<NN / 64, 64>>>(Za, (float*)d_out);
}

// round 17
// speedup vs baseline: 1.7492x; 1.7492x over previous
#include <cuda_runtime.h>
#include <cuda_bf16.h>
#include <cstdint>

// ---------------------------------------------------------------------------
// APPNP dense surrogate, N=8192, F=MLP=512, C=256, 10 power iters, alpha=0.1.
// sm_103 (non-'a'): legacy mma.sync bf16 is the fastest available tensor path
// (~290 TF/s; fp8 and int8 legacy mma measured slower, tcgen05 unavailable).
// v9 = exact R12 (2021us) bf16 pipeline + stream-forked A-convert so the
// 384MB fltr->bf16 conversion overlaps the first (A-independent) GEMM.
// Transposed-activation layout: B operand always K-major [N,K].
// ---------------------------------------------------------------------------

#define NN   8192
#define FD   512
#define CD   256
#define ALPHA 0.1f

#define BKr  64
#define STRB 144                         // smem row stride bytes (72 bf16)
#define A_TILE_B (64 * STRB)             // 9216
#define STG_B    ((64 + 128) * STRB)     // 27648
#define NSTG 4
#define SMEM_TOT (NSTG * STG_B)          // 110592 -> 2 CTAs/SM

// ---- scratch ---------------------------------------------------------------
__device__ __nv_bfloat16 g_Abf[(size_t)NN * NN];     // 128 MB
__device__ __nv_bfloat16 g_Fbf[(size_t)NN * FD];
__device__ __nv_bfloat16 g_W0t[FD * FD];
__device__ __nv_bfloat16 g_W1t[FD * FD];
__device__ __nv_bfloat16 g_Wot[FD * CD];
__device__ __nv_bfloat16 g_Yt[(size_t)FD * NN];
__device__ __nv_bfloat16 g_X[(size_t)NN * FD];
__device__ __nv_bfloat16 g_Z0t[(size_t)CD * NN];
__device__ __nv_bfloat16 g_Za[(size_t)CD * NN];
__device__ __nv_bfloat16 g_Zb[(size_t)CD * NN];

__device__ __forceinline__ uint32_t sptr(const void* p) {
    return (uint32_t)__cvta_generic_to_shared(p);
}
__device__ __forceinline__ void ldsm4(uint32_t a, uint32_t* r) {
    asm volatile("ldmatrix.sync.aligned.m8n8.x4.shared.b16 {%0,%1,%2,%3}, [%4];"
                 : "=r"(r[0]), "=r"(r[1]), "=r"(r[2]), "=r"(r[3]) : "r"(a));
}

// ---- converts --------------------------------------------------------------
__global__ void f32_to_bf16_kernel(const float* __restrict__ src,
                                   __nv_bfloat16* __restrict__ dst, long n8) {
    long t = (long)blockIdx.x * blockDim.x + threadIdx.x;
    if (t >= n8) return;
    long i = t * 8;
    float4 a = *(const float4*)(src + i);
    float4 b = *(const float4*)(src + i + 4);
    union { int4 v; __nv_bfloat16 h[8]; } u;
    u.h[0] = __float2bfloat16(a.x); u.h[1] = __float2bfloat16(a.y);
    u.h[2] = __float2bfloat16(a.z); u.h[3] = __float2bfloat16(a.w);
    u.h[4] = __float2bfloat16(b.x); u.h[5] = __float2bfloat16(b.y);
    u.h[6] = __float2bfloat16(b.z); u.h[7] = __float2bfloat16(b.w);
    *(int4*)(dst + i) = u.v;
}

__global__ void wcvt_T_kernel(const float* __restrict__ W0,
                              const float* __restrict__ W1,
                              const float* __restrict__ Wo,
                              __nv_bfloat16* __restrict__ W0t,
                              __nv_bfloat16* __restrict__ W1t,
                              __nv_bfloat16* __restrict__ Wot) {
    __shared__ float t[32][33];
    const float* src; __nv_bfloat16* dst; int C;
    if (blockIdx.z == 0)      { src = W0; dst = W0t; C = FD; }
    else if (blockIdx.z == 1) { src = W1; dst = W1t; C = FD; }
    else                      { src = Wo; dst = Wot; C = CD; }
    int c0 = blockIdx.x * 32, r0 = blockIdx.y * 32;
    if (c0 >= C) return;
    int tx = threadIdx.x, ty = threadIdx.y;   // (32, 8)
#pragma unroll
    for (int j = 0; j < 32; j += 8)
        t[ty + j][tx] = src[(size_t)(r0 + ty + j) * C + c0 + tx];
    __syncthreads();
#pragma unroll
    for (int j = 0; j < 32; j += 8)
        dst[(size_t)(c0 + ty + j) * FD + r0 + tx] = __float2bfloat16(t[tx][ty + j]);
}

// ---- v4 bf16 GEMM (proven 2021us config): C = epi(Aop @ B), Bt[N,K] -------
// MODE 0: acc + bias[row]  MODE 1: relu(acc)  MODE 2: 0.9*acc + 0.1*Z0[r,c]
template <int MODE>
__global__ void __launch_bounds__(256, 2)
gemm_v4(const __nv_bfloat16* __restrict__ Aop,
        const __nv_bfloat16* __restrict__ Btp,
        __nv_bfloat16* __restrict__ Cmat,
        int M, int N, int K,
        const float* __restrict__ bias,
        const __nv_bfloat16* __restrict__ Z0) {
    extern __shared__ char sm[];
    const uint32_t base = sptr(sm);

    const int tid  = threadIdx.x;
    const int lane = tid & 31;
    const int warp = tid >> 5;
    const int wm = (warp & 1) * 32;
    const int wn = (warp >> 1) * 32;
    const int bm0 = blockIdx.y * 64;
    const int bn0 = blockIdx.x * 128;
    const int nIter = K / BKr;

    auto load_stage = [&](int st, int kiter) {
        const int k0 = kiter * BKr;
        const uint32_t sa = base + st * STG_B;
        const uint32_t sb = sa + A_TILE_B;
#pragma unroll
        for (int i = 0; i < 2; i++) {         // A: 64 rows x 8 16B-chunks
            int id = tid + i * 256, row = id >> 3, c = id & 7;
            const void* g = Aop + (size_t)(bm0 + row) * K + k0 + c * 8;
            asm volatile("cp.async.cg.shared.global [%0], [%1], 16;\n"
                         :: "r"(sa + row * STRB + c * 16), "l"(g));
        }
#pragma unroll
        for (int i = 0; i < 4; i++) {         // B: 128 rows x 8 chunks
            int id = tid + i * 256, row = id >> 3, c = id & 7;
            const void* g = Btp + (size_t)(bn0 + row) * K + k0 + c * 8;
            asm volatile("cp.async.cg.shared.global [%0], [%1], 16;\n"
                         :: "r"(sb + row * STRB + c * 16), "l"(g));
        }
        asm volatile("cp.async.commit_group;\n");
    };

    const int lrow   = (lane & 7) + ((lane >> 3) & 1) * 8;
    const int lcol16 = (lane >> 4) * 16;
    const uint32_t aoff = (uint32_t)(wm + lrow) * STRB + lcol16;
    const uint32_t boff = (uint32_t)(wn + lrow) * STRB + lcol16;

    float acc[2][4][4];
#pragma unroll
    for (int i = 0; i < 2; i++)
#pragma unroll
        for (int j = 0; j < 4; j++)
#pragma unroll
            for (int k = 0; k < 4; k++) acc[i][j][k] = 0.f;

    load_stage(0, 0);
    load_stage(1, 1);
    load_stage(2, 2);

    for (int it = 0; it < nIter; it++) {
        asm volatile("cp.async.wait_group %0;\n" :: "n"(NSTG - 2));
        __syncthreads();

        int nxt = it + NSTG - 1;
        if (nxt < nIter) load_stage(nxt & (NSTG - 1), nxt);
        else asm volatile("cp.async.commit_group;\n");

        const uint32_t sa = base + (it & (NSTG - 1)) * STG_B;
        const uint32_t sb = sa + A_TILE_B;

#pragma unroll
        for (int kk = 0; kk < BKr / 16; kk++) {
            uint32_t af[2][4], bf[2][4];
#pragma unroll
            for (int mi = 0; mi < 2; mi++)
                ldsm4(sa + aoff + mi * 16 * STRB + kk * 32, af[mi]);
#pragma unroll
            for (int nb = 0; nb < 2; nb++)
                ldsm4(sb + boff + nb * 16 * STRB + kk * 32, bf[nb]);
            // bf[nb]: r0=b0(nj=2nb) r1=b0(nj=2nb+1) r2=b1(nj=2nb) r3=b1(nj=2nb+1)
#pragma unroll
            for (int mi = 0; mi < 2; mi++)
#pragma unroll
                for (int nj = 0; nj < 4; nj++) {
                    uint32_t b0 = bf[nj >> 1][nj & 1];
                    uint32_t b1 = bf[nj >> 1][2 + (nj & 1)];
                    asm volatile(
                        "mma.sync.aligned.m16n8k16.row.col.f32.bf16.bf16.f32 "
                        "{%0,%1,%2,%3}, {%4,%5,%6,%7}, {%8,%9}, {%0,%1,%2,%3};\n"
                        : "+f"(acc[mi][nj][0]), "+f"(acc[mi][nj][1]),
                          "+f"(acc[mi][nj][2]), "+f"(acc[mi][nj][3])
                        : "r"(af[mi][0]), "r"(af[mi][1]),
                          "r"(af[mi][2]), "r"(af[mi][3]),
                          "r"(b0), "r"(b1));
                }
        }
    }

    // --- epilogue ---
#pragma unroll
    for (int mi = 0; mi < 2; mi++) {
#pragma unroll
        for (int nj = 0; nj < 4; nj++) {
            int row0 = bm0 + wm + mi * 16 + (lane >> 2);
            int col  = bn0 + wn + nj * 8 + (lane & 3) * 2;
#pragma unroll
            for (int h = 0; h < 2; h++) {
                int row = row0 + h * 8;
                float v0 = acc[mi][nj][2 * h + 0];
                float v1 = acc[mi][nj][2 * h + 1];
                if (MODE == 0) { float b = bias[row]; v0 += b; v1 += b; }
                if (MODE == 1) { v0 = fmaxf(v0, 0.f); v1 = fmaxf(v1, 0.f); }
                if (MODE == 2) {
                    __nv_bfloat162 z = *(const __nv_bfloat162*)(Z0 + (size_t)row * N + col);
                    v0 = (1.f - ALPHA) * v0 + ALPHA * __bfloat162float(z.x);
                    v1 = (1.f - ALPHA) * v1 + ALPHA * __bfloat162float(z.y);
                }
                *(__nv_bfloat162*)(Cmat + (size_t)row * N + col) = __floats2bfloat162_rn(v0, v1);
            }
        }
    }
}

// ---- column softmax of Zt[256, 8192] -> out[8192, 256] fp32 ---------------
__global__ void softmax_T_kernel(const __nv_bfloat16* __restrict__ Zt,
                                 float* __restrict__ out) {
    __shared__ float tile[2][32][33];
    int warp = threadIdx.x >> 5, lane = threadIdx.x & 31;
    int n0 = blockIdx.x * 64 + warp * 32;
    int n = n0 + lane;

    float mx = -1e30f;
#pragma unroll 8
    for (int c = 0; c < CD; c++)
        mx = fmaxf(mx, __bfloat162float(Zt[(size_t)c * NN + n]));
    float s = 0.f;
#pragma unroll 8
    for (int c = 0; c < CD; c++)
        s += __expf(__bfloat162float(Zt[(size_t)c * NN + n]) - mx);
    float inv = 1.f / s;

    for (int c0 = 0; c0 < CD; c0 += 32) {
#pragma unroll
        for (int cc = 0; cc < 32; cc++)
            tile[warp][cc][lane] =
                __expf(__bfloat162float(Zt[(size_t)(c0 + cc) * NN + n]) - mx) * inv;
        __syncwarp();
#pragma unroll
        for (int i = 0; i < 32; i++)
            out[(size_t)(n0 + i) * CD + c0 + lane] = tile[warp][lane][i];
        __syncwarp();
    }
}

// ---------------------------------------------------------------------------
extern "C" void kernel_launch(void* const* d_in, const int* in_sizes, int n_in,
                              void* d_out, int out_size) {
    const float* features = (const float*)d_in[0];
    const float* fltr     = (const float*)d_in[1];
    const float* W0       = (const float*)d_in[2];
    const float* b0       = (const float*)d_in[3];
    const float* W1       = (const float*)d_in[4];
    const float* b1       = (const float*)d_in[5];
    const float* Wo       = (const float*)d_in[6];
    const float* bo       = (const float*)d_in[7];

    void *pA, *pF, *pW0, *pW1, *pWo, *pYt, *pX, *pZ0, *pZa, *pZb;
    cudaGetSymbolAddress(&pA,  g_Abf);
    cudaGetSymbolAddress(&pF,  g_Fbf);
    cudaGetSymbolAddress(&pW0, g_W0t);
    cudaGetSymbolAddress(&pW1, g_W1t);
    cudaGetSymbolAddress(&pWo, g_Wot);
    cudaGetSymbolAddress(&pYt, g_Yt);
    cudaGetSymbolAddress(&pX,  g_X);
    cudaGetSymbolAddress(&pZ0, g_Z0t);
    cudaGetSymbolAddress(&pZa, g_Za);
    cudaGetSymbolAddress(&pZb, g_Zb);

    __nv_bfloat16* Abf = (__nv_bfloat16*)pA;
    __nv_bfloat16* Fbf = (__nv_bfloat16*)pF;
    __nv_bfloat16* W0t = (__nv_bfloat16*)pW0;
    __nv_bfloat16* W1t = (__nv_bfloat16*)pW1;
    __nv_bfloat16* Wot = (__nv_bfloat16*)pWo;
    __nv_bfloat16* Yt  = (__nv_bfloat16*)pYt;
    __nv_bfloat16* Xb  = (__nv_bfloat16*)pX;
    __nv_bfloat16* Z0t = (__nv_bfloat16*)pZ0;
    __nv_bfloat16* Za  = (__nv_bfloat16*)pZa;
    __nv_bfloat16* Zb  = (__nv_bfloat16*)pZb;

    cudaFuncSetAttribute(gemm_v4<0>, cudaFuncAttributeMaxDynamicSharedMemorySize, SMEM_TOT);
    cudaFuncSetAttribute(gemm_v4<1>, cudaFuncAttributeMaxDynamicSharedMemorySize, SMEM_TOT);
    cudaFuncSetAttribute(gemm_v4<2>, cudaFuncAttributeMaxDynamicSharedMemorySize, SMEM_TOT);

    // lazily-created side stream + events (first call is outside capture;
    // reused handles are capture-safe; no device allocations involved)
    static cudaStream_t s_side = nullptr;
    static cudaEvent_t  s_fork = nullptr, s_join = nullptr;
    if (!s_side) {
        cudaStreamCreateWithFlags(&s_side, cudaStreamNonBlocking);
        cudaEventCreateWithFlags(&s_fork, cudaEventDisableTiming);
        cudaEventCreateWithFlags(&s_join, cudaEventDisableTiming);
    }

    // 0) fork: A-convert (biggest, A-independent consumers come later) runs on
    //    the side stream while the main stream does small converts + GEMM 1.
    cudaEventRecord(s_fork, 0);
    cudaStreamWaitEvent(s_side, s_fork, 0);
    {
        long n8 = (long)NN * NN / 8;
        f32_to_bf16_kernel<<<(int)((n8 + 255) / 256), 256, 0, s_side>>>(fltr, Abf, n8);
    }
    cudaEventRecord(s_join, s_side);

    // main stream: small converts
    {
        long f8 = (long)NN * FD / 8;
        f32_to_bf16_kernel<<<(int)((f8 + 255) / 256), 256>>>(features, Fbf, f8);
        wcvt_T_kernel<<<dim3(16, 16, 3), dim3(32, 8)>>>(W0, W1, Wo, W0t, W1t, Wot);
    }

    dim3 gridYt(NN / 128, FD / 64);    // (64, 8)  = 512 CTAs  [512,8192]
    dim3 gridX (FD / 128, NN / 64);    // (4, 128) = 512 CTAs  [8192,512]
    dim3 gridZ (NN / 128, CD / 64);    // (64, 4)  = 256 CTAs  [256,8192]

    // 1) Yt = W0t @ Ft (+b0 row)   — A-independent, overlaps the A-convert
    gemm_v4<0><<<gridYt, 256, SMEM_TOT>>>(W0t, Fbf, Yt, FD, NN, FD, b0, nullptr);

    // join: A must be converted before step 2
    cudaStreamWaitEvent(0, s_join, 0);

    // 2) X = relu(A @ Y)   (Bt = Yt)
    gemm_v4<1><<<gridX, 256, SMEM_TOT>>>(Abf, Yt, Xb, NN, FD, NN, nullptr, nullptr);
    // 3) Yt = W1t @ Xt (+b1 row)
    gemm_v4<0><<<gridYt, 256, SMEM_TOT>>>(W1t, Xb, Yt, FD, NN, FD, b1, nullptr);
    // 4) X = relu(A @ Y2)
    gemm_v4<1><<<gridX, 256, SMEM_TOT>>>(Abf, Yt, Xb, NN, FD, NN, nullptr, nullptr);
    // 5) Z0t = Wot @ X2t (+bo row)
    gemm_v4<0><<<gridZ, 256, SMEM_TOT>>>(Wot, Xb, Z0t, CD, NN, FD, bo, nullptr);

    // 6) 10x: Zt = 0.9 * Zt @ At + 0.1 * Z0t   (Bt = A natural)
    __nv_bfloat16* zin = Z0t;
    __nv_bfloat16* zout = Za;
    for (int it = 0; it < 10; it++) {
        gemm_v4<2><<<gridZ, 256, SMEM_TOT>>>(zin, Abf, zout, CD, NN, NN, nullptr, Z0t);
        zin = zout;
        zout = (zin == Za) ? Zb : Za;
    }

    // 7) column softmax -> [8192, 256] fp32
    softmax_T_kernel<<<NN / 64, 64>>>(zin, (float*)d_out);
}